// round 3
// baseline (speedup 1.0000x reference)
#include <cuda_runtime.h>
#include <math.h>

#define SQ 1024
#define HD 4096
#define VOCAB 32000
#define KK2 8192          // 2*HD
#define TK 10
#define NDEPTH 5
#define NTOTAL 59
#define NFLAT (TK + NDEPTH*TK*TK)   // 510
#define NPAR (1 + NDEPTH*TK)        // 51
#define NCH 32            // chunks per row for top-k phase 1
#define CHUNK 1000        // VOCAB / NCH

// ---------------- scratch (device globals; no allocation allowed) ----------------
__device__ float g_x[TK * KK2];          // concat(emb, hidden) rows
__device__ float g_fc[TK * HD];          // fc output
__device__ float g_hid[TK * HD];         // out_hidden (tanh)
__device__ float g_hid_sel[TK * HD];     // gathered input_hidden for next step
__device__ float g_logits[TK * VOCAB];
__device__ float g_topk_p[TK * TK];      // per-row top-k log-probs
__device__ int   g_topk_i[TK * TK];      // per-row top-k vocab ids
__device__ float g_scores[TK];           // cumulative path scores
__device__ int   g_cs_index[TK];         // last topk_cs_index
__device__ int   g_cur_ids[TK];
__device__ int   g_out_ids[TK];
__device__ float g_scores_flat[NFLAT];
__device__ int   g_tokens_flat[NFLAT];
__device__ int   g_parents_flat[NPAR];
// top-k phase-1 partials
__device__ float g_pmax[TK * NCH];
__device__ float g_psum[TK * NCH];
__device__ float g_ptopv[TK * NCH * TK];
__device__ int   g_ptopi[TK * NCH * TK];

// ---------------- build concat input rows ----------------
__global__ void build_x0_kernel(const float* __restrict__ hidden,
                                const int* __restrict__ input_ids,
                                const float* __restrict__ W_embed) {
    int j = blockIdx.x * blockDim.x + threadIdx.x;
    if (j < HD) {
        int id = input_ids[SQ];                      // ids[:, -1] == input_ids[0, S]
        g_x[j]      = W_embed[(size_t)id * HD + j];
        g_x[HD + j] = hidden[(size_t)(SQ - 1) * HD + j];
    }
}

__global__ void build_x_kernel(const float* __restrict__ W_embed) {
    int j = blockIdx.x * blockDim.x + threadIdx.x;
    int r = blockIdx.y;
    if (j < HD) {
        int id = g_cur_ids[r];
        g_x[(size_t)r * KK2 + j]      = W_embed[(size_t)id * HD + j];
        g_x[(size_t)r * KK2 + HD + j] = g_hid_sel[(size_t)r * HD + j];
    }
}

// ---------------- GEMV: out[r][n] = act(sum_k X[r][k] * W[n][k] + b[n]) ----------------
template <int R, bool TANH>
__global__ void __launch_bounds__(256)
gemv_kernel(const float* __restrict__ X, const float* __restrict__ W,
            const float* __restrict__ bias, float* __restrict__ out,
            int N, int K) {
    int warp = threadIdx.x >> 5;
    int lane = threadIdx.x & 31;
    int n0 = (blockIdx.x * 8 + warp) * 2;
    if (n0 >= N) return;
    const float4* W0 = (const float4*)(W + (size_t)n0 * K);
    const float4* W1 = (const float4*)(W + (size_t)(n0 + 1) * K);
    float acc0[R], acc1[R];
#pragma unroll
    for (int r = 0; r < R; ++r) { acc0[r] = 0.f; acc1[r] = 0.f; }
    const int nq = K >> 2;
    for (int q = lane; q < nq; q += 32) {
        float4 a = __ldg(W0 + q);
        float4 b = __ldg(W1 + q);
#pragma unroll
        for (int r = 0; r < R; ++r) {
            float4 xv = __ldg((const float4*)(X + (size_t)r * K) + q);
            acc0[r] += a.x * xv.x; acc0[r] += a.y * xv.y;
            acc0[r] += a.z * xv.z; acc0[r] += a.w * xv.w;
            acc1[r] += b.x * xv.x; acc1[r] += b.y * xv.y;
            acc1[r] += b.z * xv.z; acc1[r] += b.w * xv.w;
        }
    }
#pragma unroll
    for (int r = 0; r < R; ++r) {
#pragma unroll
        for (int off = 16; off > 0; off >>= 1) {
            acc0[r] += __shfl_down_sync(0xffffffffu, acc0[r], off);
            acc1[r] += __shfl_down_sync(0xffffffffu, acc1[r], off);
        }
    }
    if (lane == 0) {
        float b0 = bias ? bias[n0] : 0.f;
        float b1 = bias ? bias[n0 + 1] : 0.f;
#pragma unroll
        for (int r = 0; r < R; ++r) {
            float v0 = acc0[r] + b0;
            float v1 = acc1[r] + b1;
            if (TANH) { v0 = tanhf(v0); v1 = tanhf(v1); }
            out[(size_t)r * N + n0]     = v0;
            out[(size_t)r * N + n0 + 1] = v1;
        }
    }
}

// ---------------- top-k phase 1: per-chunk max / sumexp / local top-10 ----------------
// grid: (NCH, rows). block: 256. One pass over the chunk, then smem-only rounds.
__global__ void __launch_bounds__(256) topk_p1_kernel() {
    int chunk = blockIdx.x, r = blockIdx.y;
    const float* logits = g_logits + (size_t)r * VOCAB + chunk * CHUNK;
    __shared__ float vals[CHUNK];
    __shared__ float s_val[256];
    __shared__ int   s_idx[256];
    int t = threadIdx.x;

    float m = -INFINITY;
    for (int v = t; v < CHUNK; v += 256) {
        float x = logits[v];
        vals[v] = x;
        m = fmaxf(m, x);
    }
    s_val[t] = m;
    __syncthreads();
    for (int s = 128; s > 0; s >>= 1) {
        if (t < s) s_val[t] = fmaxf(s_val[t], s_val[t + s]);
        __syncthreads();
    }
    float cmax = s_val[0];
    __syncthreads();

    float sum = 0.f;
    for (int v = t; v < CHUNK; v += 256) sum += expf(vals[v] - cmax);
    s_val[t] = sum;
    __syncthreads();
    for (int s = 128; s > 0; s >>= 1) {
        if (t < s) s_val[t] += s_val[t + s];
        __syncthreads();
    }
    if (t == 0) {
        g_pmax[r * NCH + chunk] = cmax;
        g_psum[r * NCH + chunk] = s_val[0];
    }
    __syncthreads();

    // 10 destructive argmax rounds over smem (tie-break: lowest index)
    for (int k = 0; k < TK; ++k) {
        float best = -INFINITY;
        int bi = 0x7fffffff;
        for (int v = t; v < CHUNK; v += 256) {
            float x = vals[v];
            if (x > best || (x == best && v < bi)) { best = x; bi = v; }
        }
        s_val[t] = best; s_idx[t] = bi;
        __syncthreads();
        for (int s = 128; s > 0; s >>= 1) {
            if (t < s) {
                float ov = s_val[t + s]; int oi = s_idx[t + s];
                if (ov > s_val[t] || (ov == s_val[t] && oi < s_idx[t])) {
                    s_val[t] = ov; s_idx[t] = oi;
                }
            }
            __syncthreads();
        }
        if (t == 0) {
            g_ptopv[(r * NCH + chunk) * TK + k] = s_val[0];
            g_ptopi[(r * NCH + chunk) * TK + k] = chunk * CHUNK + s_idx[0];
            vals[s_idx[0]] = -INFINITY;
        }
        __syncthreads();
    }
}

// ---------------- top-k phase 2: merge 32 partials per row ----------------
// grid: rows. block: 320 threads (one per candidate).
__global__ void __launch_bounds__(320) topk_p2_kernel() {
    int r = blockIdx.x;
    int t = threadIdx.x;
    const int NC = NCH * TK;   // 320 candidates
    __shared__ float cv[NC];
    __shared__ int   ci[NC];
    __shared__ float s_val[NC];
    __shared__ int   s_idx[NC];
    __shared__ float s_lse;

    cv[t] = g_ptopv[r * NC + t];
    ci[t] = g_ptopi[r * NC + t];

    if (t == 0) {
        float gmax = -INFINITY;
        for (int b = 0; b < NCH; ++b) gmax = fmaxf(gmax, g_pmax[r * NCH + b]);
        float sum = 0.f;
        for (int b = 0; b < NCH; ++b)
            sum += g_psum[r * NCH + b] * expf(g_pmax[r * NCH + b] - gmax);
        s_lse = gmax + logf(sum);
    }
    __syncthreads();
    float lse = s_lse;

    for (int k = 0; k < TK; ++k) {
        s_val[t] = cv[t]; s_idx[t] = ci[t];
        __syncthreads();
        // 320 -> 64 -> tree
        if (t < 64) {
            float bv = s_val[t]; int bi = s_idx[t];
            for (int j = t + 64; j < NC; j += 64) {
                float ov = s_val[j]; int oi = s_idx[j];
                if (ov > bv || (ov == bv && oi < bi)) { bv = ov; bi = oi; }
            }
            s_val[t] = bv; s_idx[t] = bi;
        }
        __syncthreads();
        for (int s = 32; s > 0; s >>= 1) {
            if (t < s) {
                float ov = s_val[t + s]; int oi = s_idx[t + s];
                if (ov > s_val[t] || (ov == s_val[t] && oi < s_idx[t])) {
                    s_val[t] = ov; s_idx[t] = oi;
                }
            }
            __syncthreads();
        }
        if (t == 0) {
            g_topk_p[r * TK + k] = s_val[0] - lse;
            g_topk_i[r * TK + k] = s_idx[0];
        }
        // invalidate winner (it's a unique (val,idx) pair; clear by idx match)
        if (ci[t] == s_idx[0] && cv[t] == s_val[0]) cv[t] = -INFINITY;
        __syncthreads();
    }
}

// ---------------- after the initial (pre-loop) top-k ----------------
__global__ void post0_kernel() {
    int j = blockIdx.x * blockDim.x + threadIdx.x;
    if (j < HD) {
        float v = g_hid[j];   // last_hidden broadcast to all 10 rows
#pragma unroll
        for (int r = 0; r < TK; ++r) g_hid_sel[(size_t)r * HD + j] = v;
    }
    if (blockIdx.x == 0 && j < TK) {
        float p = g_topk_p[j];
        int id = g_topk_i[j];
        g_scores[j] = p;
        g_scores_flat[j] = p;
        g_tokens_flat[j] = id;
        g_cur_ids[j] = id;
        g_cs_index[j] = j;
        if (j == 0) g_parents_flat[0] = 0;
    }
}

// ---------------- cross-row merge for depth iteration `iter` ----------------
__global__ void combine_kernel(int iter) {
    __shared__ float cu[TK * TK];
    __shared__ float sc_old[TK];
    __shared__ int prev_cs[TK];
    int t = threadIdx.x;
    if (t < TK) { sc_old[t] = g_scores[t]; prev_cs[t] = g_cs_index[t]; }
    __syncthreads();
    if (t < TK * TK) cu[t] = g_topk_p[t] + sc_old[t / TK];
    __syncthreads();
    if (t < TK * TK) {
        g_scores_flat[TK + iter * 100 + t] = cu[t];
        g_tokens_flat[TK + iter * 100 + t] = g_topk_i[t];
    }
    if (t < TK) {
        int bias1 = (iter > 0) ? TK : 0;
        int bias2 = (iter > 1) ? (iter - 1) : 0;
        int bias = 1 + TK * TK * bias2 + bias1;
        g_parents_flat[1 + iter * TK + t] = prev_cs[t] + bias;
    }
    __syncthreads();
    if (t == 0) {
        bool used[TK * TK];
        for (int j = 0; j < TK * TK; ++j) used[j] = false;
        for (int k = 0; k < TK; ++k) {
            float best = -INFINITY; int bi = 0;
            for (int j = 0; j < TK * TK; ++j)
                if (!used[j] && cu[j] > best) { best = cu[j]; bi = j; }
            used[bi] = true;
            g_scores[k]   = best;
            g_cs_index[k] = bi;
            g_out_ids[k]  = bi / TK;
            g_cur_ids[k]  = g_topk_i[bi];
        }
    }
}

__global__ void gather_hidden_kernel() {
    int j = blockIdx.x * blockDim.x + threadIdx.x;
    int r = blockIdx.y;
    if (j < HD)
        g_hid_sel[(size_t)r * HD + j] = g_hid[(size_t)g_out_ids[r] * HD + j];
}

// ---------------- final: top-59, sort, parents, tree mask, outputs ----------------
__global__ void finalize_kernel(const int* __restrict__ input_ids, float* __restrict__ out) {
    __shared__ float sc[NFLAT];
    __shared__ int top_idx[NTOTAL];
    __shared__ int mask_idx[NTOTAL];
    __shared__ unsigned long long rows[NTOTAL + 1];
    int t = threadIdx.x, T = blockDim.x;
    for (int j = t; j < NFLAT; j += T) sc[j] = g_scores_flat[j];
    __syncthreads();
    if (t == 0) {
        for (int k = 0; k < NTOTAL; ++k) {
            float best = -INFINITY; int bi = 0;
            for (int j = 0; j < NFLAT; ++j)
                if (sc[j] > best) { best = sc[j]; bi = j; }
            top_idx[k] = bi;
            sc[bi] = -INFINITY;
        }
        for (int a = 1; a < NTOTAL; ++a) {
            int v = top_idx[a], b = a - 1;
            while (b >= 0 && top_idx[b] > v) { top_idx[b + 1] = top_idx[b]; --b; }
            top_idx[b + 1] = v;
        }
    }
    __syncthreads();
    if (t == 0) out[0] = (float)input_ids[SQ];   // sample_token
    for (int k = t; k < NTOTAL; k += T) {
        int idx = top_idx[k];
        out[1 + k]  = (float)g_tokens_flat[idx]; // draft_tokens[1..59]
        out[60 + k] = g_scores_flat[idx];        // top_vals
    }
    __syncthreads();
    if (t == 0) {
        for (int k = 0; k < NTOTAL; ++k) {
            int p = g_parents_flat[top_idx[k] / TK];
            int mi;
            if (p == 0) {
                mi = 0;
            } else {
                int target = p - 1;
                int lo = 0, hi = NTOTAL;
                while (lo < hi) {
                    int mid = (lo + hi) >> 1;
                    if (top_idx[mid] < target) lo = mid + 1; else hi = mid;
                }
                mi = lo + 1;
            }
            mask_idx[k] = mi;
        }
        for (int r = 0; r < NTOTAL + 1; ++r)
            rows[r] = (1ULL << r) | 1ULL;
        for (int i = 0; i < NTOTAL; ++i) {
            int src = mask_idx[i];
            if (src > NTOTAL) src = NTOTAL;
            rows[i + 1] |= rows[src];
        }
    }
    __syncthreads();
    for (int e = t; e < (NTOTAL + 1) * (NTOTAL + 1); e += T) {
        int r = e / (NTOTAL + 1), c = e % (NTOTAL + 1);
        out[119 + e] = ((rows[r] >> c) & 1ULL) ? 1.0f : 0.0f;
    }
    for (int r = t; r < NTOTAL + 1; r += T)
        out[3719 + r] = (float)(__popcll(rows[r]) - 1);
}

// ---------------- launch ----------------
extern "C" void kernel_launch(void* const* d_in, const int* in_sizes, int n_in,
                              void* d_out, int out_size) {
    const float* hidden    = (const float*)d_in[0];
    const int*   input_ids = (const int*)d_in[1];
    const float* W_embed   = (const float*)d_in[2];
    const float* W_head    = (const float*)d_in[3];
    const float* W_fc      = (const float*)d_in[4];
    const float* b_fc      = (const float*)d_in[5];
    const float* W_m       = (const float*)d_in[6];
    const float* b_m       = (const float*)d_in[7];
    float* out = (float*)d_out;

    float *p_x, *p_fc, *p_hid, *p_logits;
    cudaGetSymbolAddress((void**)&p_x,      g_x);
    cudaGetSymbolAddress((void**)&p_fc,     g_fc);
    cudaGetSymbolAddress((void**)&p_hid,    g_hid);
    cudaGetSymbolAddress((void**)&p_logits, g_logits);

    // ---- initial step (only last position matters) ----
    build_x0_kernel<<<HD / 256, 256>>>(hidden, input_ids, W_embed);
    gemv_kernel<1, false><<<HD / 16, 256>>>(p_x, W_fc, b_fc, p_fc, HD, KK2);
    gemv_kernel<1, true ><<<HD / 16, 256>>>(p_fc, W_m, b_m, p_hid, HD, HD);
    gemv_kernel<1, false><<<VOCAB / 16, 256>>>(p_hid, W_head, nullptr, p_logits, VOCAB, HD);
    topk_p1_kernel<<<dim3(NCH, 1), 256>>>();
    topk_p2_kernel<<<1, 320>>>();
    post0_kernel<<<HD / 256, 256>>>();

    // ---- depth loop ----
    for (int i = 0; i < NDEPTH; ++i) {
        build_x_kernel<<<dim3(HD / 256, TK), 256>>>(W_embed);
        gemv_kernel<TK, false><<<HD / 16, 256>>>(p_x, W_fc, b_fc, p_fc, HD, KK2);
        gemv_kernel<TK, true ><<<HD / 16, 256>>>(p_fc, W_m, b_m, p_hid, HD, HD);
        gemv_kernel<TK, false><<<VOCAB / 16, 256>>>(p_hid, W_head, nullptr, p_logits, VOCAB, HD);
        topk_p1_kernel<<<dim3(NCH, TK), 256>>>();
        topk_p2_kernel<<<TK, 320>>>();
        combine_kernel<<<1, 128>>>(i);
        if (i < NDEPTH - 1)
            gather_hidden_kernel<<<dim3(HD / 256, TK), 256>>>();
    }

    finalize_kernel<<<1, 256>>>(input_ids, out);
    (void)in_sizes; (void)n_in; (void)out_size;
}

// round 6
// speedup vs baseline: 1.5446x; 1.5446x over previous
#include <cuda_runtime.h>
#include <math.h>

#define SQ 1024
#define HD 4096
#define VOCAB 32000
#define KK2 8192          // 2*HD
#define TK 10
#define NDEPTH 5
#define NTOTAL 59
#define NFLAT (TK + NDEPTH*TK*TK)   // 510
#define NPAR (1 + NDEPTH*TK)        // 51
#define NCH 25            // chunks per row for top-k phase 1
#define CHUNK 1280        // VOCAB / NCH = 256*5
#define KCHUNK 2048       // GEMV K tile (floats)

// ---------------- scratch (device globals; no allocation allowed) ----------------
__device__ float g_fc[TK * HD];          // fc output
__device__ float g_hid[TK * HD];         // out_hidden (tanh)
__device__ float g_logits[TK * VOCAB];
__device__ float g_topk_p[TK * TK];      // per-row top-k log-probs
__device__ int   g_topk_i[TK * TK];      // per-row top-k vocab ids
__device__ float g_scores[TK];           // cumulative path scores
__device__ int   g_cs_index[TK];         // last topk_cs_index
__device__ int   g_cur_ids[TK];
__device__ int   g_out_ids[TK];
__device__ float g_scores_flat[NFLAT];
__device__ int   g_tokens_flat[NFLAT];
__device__ int   g_parents_flat[NPAR];
// top-k phase-1 partials
__device__ float g_pmax[TK * NCH];
__device__ float g_psum[TK * NCH];
__device__ float g_ptopv[TK * NCH * TK];
__device__ int   g_ptopi[TK * NCH * TK];

// ---------------- init: zero g_out_ids before the first GATHER GEMV ----------------
__global__ void init_kernel() {
    if (threadIdx.x < TK) g_out_ids[threadIdx.x] = 0;
}

// ---------------- GEMV with smem-staged X, 4 cols/warp ----------------
// out[r][n] = act(sum_k X[r][k] * W[n][k] + b[n])
// GATHER mode builds X[r] = concat(W_embed[curids[r]], Xbase[outids[r]]) on the fly.
template <int R, bool TANH, bool GATHER>
__global__ void __launch_bounds__(256)
gemv2_kernel(const float* __restrict__ Xbase,   // direct: X (R rows, stride K); gather: hidden base (stride HD)
             const float* __restrict__ W,
             const float* __restrict__ bias,
             float* __restrict__ out,
             int N, int K,
             const float* __restrict__ Wemb,
             const int* __restrict__ curids,
             const int* __restrict__ outids)
{
    extern __shared__ float sx[];            // R * KCHUNK floats
    float4* sx4 = (float4*)sx;
    const int t = threadIdx.x;
    const int warp = t >> 5, lane = t & 31;
    const int n0 = blockIdx.x * 32 + warp * 4;

    float acc[4][R];
#pragma unroll
    for (int c = 0; c < 4; ++c)
#pragma unroll
        for (int r = 0; r < R; ++r) acc[c][r] = 0.f;

    const int QC = KCHUNK / 4;               // 512 float4 per row-chunk
    const int nchunks = K / KCHUNK;
    for (int kc = 0; kc < nchunks; ++kc) {
        const int base_k = kc * KCHUNK;
        // ---- stage X chunk ----
        for (int idx = t; idx < R * QC; idx += 256) {
            int r = idx / QC;
            int kk4 = idx - r * QC;
            int k = base_k + kk4 * 4;
            float4 v;
            if (GATHER) {
                if (k < HD) {
                    int id = __ldg(curids + r);
                    v = *(const float4*)(Wemb + (size_t)id * HD + k);
                } else {
                    int orow = __ldg(outids + r);
                    v = *(const float4*)(Xbase + (size_t)orow * HD + (k - HD));
                }
            } else {
                v = *(const float4*)(Xbase + (size_t)r * K + k);
            }
            sx4[idx] = v;
        }
        __syncthreads();
        // ---- accumulate ----
        const float4* w0 = (const float4*)(W + (size_t)(n0 + 0) * K + base_k);
        const float4* w1 = (const float4*)(W + (size_t)(n0 + 1) * K + base_k);
        const float4* w2 = (const float4*)(W + (size_t)(n0 + 2) * K + base_k);
        const float4* w3 = (const float4*)(W + (size_t)(n0 + 3) * K + base_k);
        for (int q = lane; q < QC; q += 32) {
            float4 a0 = __ldg(w0 + q);
            float4 a1 = __ldg(w1 + q);
            float4 a2 = __ldg(w2 + q);
            float4 a3 = __ldg(w3 + q);
#pragma unroll
            for (int r = 0; r < R; ++r) {
                float4 xv = sx4[r * QC + q];
                acc[0][r] += a0.x*xv.x; acc[0][r] += a0.y*xv.y; acc[0][r] += a0.z*xv.z; acc[0][r] += a0.w*xv.w;
                acc[1][r] += a1.x*xv.x; acc[1][r] += a1.y*xv.y; acc[1][r] += a1.z*xv.z; acc[1][r] += a1.w*xv.w;
                acc[2][r] += a2.x*xv.x; acc[2][r] += a2.y*xv.y; acc[2][r] += a2.z*xv.z; acc[2][r] += a2.w*xv.w;
                acc[3][r] += a3.x*xv.x; acc[3][r] += a3.y*xv.y; acc[3][r] += a3.z*xv.z; acc[3][r] += a3.w*xv.w;
            }
        }
        __syncthreads();
    }
    // ---- warp reduce + write ----
#pragma unroll
    for (int c = 0; c < 4; ++c)
#pragma unroll
        for (int r = 0; r < R; ++r) {
            float a = acc[c][r];
#pragma unroll
            for (int off = 16; off > 0; off >>= 1)
                a += __shfl_down_sync(0xffffffffu, a, off);
            acc[c][r] = a;
        }
    if (lane == 0) {
#pragma unroll
        for (int c = 0; c < 4; ++c) {
            float b = bias ? bias[n0 + c] : 0.f;
#pragma unroll
            for (int r = 0; r < R; ++r) {
                float v = acc[c][r] + b;
                if (TANH) v = tanhf(v);
                out[(size_t)r * N + n0 + c] = v;
            }
        }
    }
}

// ---------------- top-k phase 1 ----------------
// grid (NCH, rows), 256 threads; chunk of 1280, 5 values/thread.
__global__ void __launch_bounds__(256) topk_p1_kernel() {
    const int chunk = blockIdx.x, r = blockIdx.y;
    const float* lp = g_logits + (size_t)r * VOCAB + chunk * CHUNK;
    const int gbase = chunk * CHUNK;
    __shared__ float sval[CHUNK];
    __shared__ float wred_v[8];
    __shared__ int   wred_i[8];
    const int t = threadIdx.x, lane = t & 31, wid = t >> 5;

    float v[5];
#pragma unroll
    for (int j = 0; j < 5; ++j) {
        float x = lp[t + j * 256];
        v[j] = x;
        sval[t + j * 256] = x;
    }
    // chunk max
    float m = fmaxf(fmaxf(fmaxf(v[0], v[1]), fmaxf(v[2], v[3])), v[4]);
#pragma unroll
    for (int off = 16; off > 0; off >>= 1)
        m = fmaxf(m, __shfl_xor_sync(0xffffffffu, m, off));
    if (lane == 0) wred_v[wid] = m;
    __syncthreads();
    if (t == 0) {
        float mm = wred_v[0];
#pragma unroll
        for (int w = 1; w < 8; ++w) mm = fmaxf(mm, wred_v[w]);
        wred_v[0] = mm;
    }
    __syncthreads();
    float cmax = wred_v[0];
    __syncthreads();
    // sum exp
    float s = 0.f;
#pragma unroll
    for (int j = 0; j < 5; ++j) s += expf(v[j] - cmax);
#pragma unroll
    for (int off = 16; off > 0; off >>= 1)
        s += __shfl_xor_sync(0xffffffffu, s, off);
    if (lane == 0) wred_v[wid] = s;
    __syncthreads();
    if (t == 0) {
        float ss = 0.f;
#pragma unroll
        for (int w = 0; w < 8; ++w) ss += wred_v[w];
        g_pmax[r * NCH + chunk] = cmax;
        g_psum[r * NCH + chunk] = ss;
    }
    __syncthreads();

    // 10 destructive argmax rounds (tie-break: lowest index)
    for (int k = 0; k < TK; ++k) {
        float bv = -INFINITY; int bi = 0x7fffffff;
#pragma unroll
        for (int j = 0; j < 5; ++j) {
            int l = t + j * 256;
            float x = sval[l];
            if (x > bv || (x == bv && l < bi)) { bv = x; bi = l; }
        }
#pragma unroll
        for (int off = 16; off > 0; off >>= 1) {
            float ov = __shfl_xor_sync(0xffffffffu, bv, off);
            int   oi = __shfl_xor_sync(0xffffffffu, bi, off);
            if (ov > bv || (ov == bv && oi < bi)) { bv = ov; bi = oi; }
        }
        if (lane == 0) { wred_v[wid] = bv; wred_i[wid] = bi; }
        __syncthreads();
        if (t == 0) {
            float Bv = wred_v[0]; int Bi = wred_i[0];
#pragma unroll
            for (int w = 1; w < 8; ++w) {
                float ov = wred_v[w]; int oi = wred_i[w];
                if (ov > Bv || (ov == Bv && oi < Bi)) { Bv = ov; Bi = oi; }
            }
            g_ptopv[(r * NCH + chunk) * TK + k] = Bv;
            g_ptopi[(r * NCH + chunk) * TK + k] = gbase + Bi;
            sval[Bi] = -INFINITY;
        }
        __syncthreads();
    }
}

// ---------------- top-k phase 2: merge 25*10 candidates + lse ----------------
__global__ void __launch_bounds__(256) topk_p2_kernel() {
    const int r = blockIdx.x, t = threadIdx.x, lane = t & 31, wid = t >> 5;
    const int NC = NCH * TK;   // 250
    __shared__ float cv[256];
    __shared__ int   ci[256];
    __shared__ float wv[8];
    __shared__ int   wi[8];
    __shared__ float s_lse;
    __shared__ int   s_win;

    cv[t] = (t < NC) ? g_ptopv[r * NC + t] : -INFINITY;
    ci[t] = (t < NC) ? g_ptopi[r * NC + t] : 0x7fffffff;
    if (t == 0) {
        float gmax = -INFINITY;
        for (int b = 0; b < NCH; ++b) gmax = fmaxf(gmax, g_pmax[r * NCH + b]);
        float sum = 0.f;
        for (int b = 0; b < NCH; ++b)
            sum += g_psum[r * NCH + b] * expf(g_pmax[r * NCH + b] - gmax);
        s_lse = gmax + logf(sum);
    }
    __syncthreads();
    float lse = s_lse;

    for (int k = 0; k < TK; ++k) {
        float bv = cv[t]; int bi = ci[t];
#pragma unroll
        for (int off = 16; off > 0; off >>= 1) {
            float ov = __shfl_xor_sync(0xffffffffu, bv, off);
            int   oi = __shfl_xor_sync(0xffffffffu, bi, off);
            if (ov > bv || (ov == bv && oi < bi)) { bv = ov; bi = oi; }
        }
        if (lane == 0) { wv[wid] = bv; wi[wid] = bi; }
        __syncthreads();
        if (t == 0) {
            float Bv = wv[0]; int Bi = wi[0];
#pragma unroll
            for (int w = 1; w < 8; ++w) {
                float ov = wv[w]; int oi = wi[w];
                if (ov > Bv || (ov == Bv && oi < Bi)) { Bv = ov; Bi = oi; }
            }
            g_topk_p[r * TK + k] = Bv - lse;
            g_topk_i[r * TK + k] = Bi;
            s_win = Bi;
        }
        __syncthreads();
        if (ci[t] == s_win) cv[t] = -INFINITY;
        __syncthreads();
    }
}

// ---------------- after the initial (pre-loop) top-k ----------------
__global__ void post0_kernel() {
    int t = threadIdx.x;
    if (t < TK) {
        float p = g_topk_p[t];
        int id = g_topk_i[t];
        g_scores[t] = p;
        g_scores_flat[t] = p;
        g_tokens_flat[t] = id;
        g_cur_ids[t] = id;
        g_cs_index[t] = t;
        g_out_ids[t] = 0;      // broadcast last_hidden (g_hid row 0)
        if (t == 0) g_parents_flat[0] = 0;
    }
}

// ---------------- cross-row merge for depth iteration `iter` ----------------
__global__ void combine_kernel(int iter) {
    __shared__ float cu[TK * TK];
    __shared__ float sc_old[TK];
    __shared__ int prev_cs[TK];
    int t = threadIdx.x;
    if (t < TK) { sc_old[t] = g_scores[t]; prev_cs[t] = g_cs_index[t]; }
    __syncthreads();
    if (t < TK * TK) cu[t] = g_topk_p[t] + sc_old[t / TK];
    __syncthreads();
    if (t < TK * TK) {
        g_scores_flat[TK + iter * 100 + t] = cu[t];
        g_tokens_flat[TK + iter * 100 + t] = g_topk_i[t];
    }
    if (t < TK) {
        int bias1 = (iter > 0) ? TK : 0;
        int bias2 = (iter > 1) ? (iter - 1) : 0;
        int bias = 1 + TK * TK * bias2 + bias1;
        g_parents_flat[1 + iter * TK + t] = prev_cs[t] + bias;
    }
    __syncthreads();
    if (t == 0) {
        bool used[TK * TK];
        for (int j = 0; j < TK * TK; ++j) used[j] = false;
        for (int k = 0; k < TK; ++k) {
            float best = -INFINITY; int bi = 0;
            for (int j = 0; j < TK * TK; ++j)
                if (!used[j] && cu[j] > best) { best = cu[j]; bi = j; }
            used[bi] = true;
            g_scores[k]   = best;
            g_cs_index[k] = bi;
            g_out_ids[k]  = bi / TK;
            g_cur_ids[k]  = g_topk_i[bi];
        }
    }
}

// ---------------- final: top-59, sort, parents, tree mask, outputs ----------------
__global__ void finalize_kernel(const int* __restrict__ input_ids, float* __restrict__ out) {
    __shared__ float sc[NFLAT];
    __shared__ int top_idx[NTOTAL];
    __shared__ int mask_idx[NTOTAL];
    __shared__ unsigned long long rows[NTOTAL + 1];
    int t = threadIdx.x, T = blockDim.x;
    for (int j = t; j < NFLAT; j += T) sc[j] = g_scores_flat[j];
    __syncthreads();
    if (t == 0) {
        for (int k = 0; k < NTOTAL; ++k) {
            float best = -INFINITY; int bi = 0;
            for (int j = 0; j < NFLAT; ++j)
                if (sc[j] > best) { best = sc[j]; bi = j; }
            top_idx[k] = bi;
            sc[bi] = -INFINITY;
        }
        for (int a = 1; a < NTOTAL; ++a) {
            int v = top_idx[a], b = a - 1;
            while (b >= 0 && top_idx[b] > v) { top_idx[b + 1] = top_idx[b]; --b; }
            top_idx[b + 1] = v;
        }
    }
    __syncthreads();
    if (t == 0) out[0] = (float)input_ids[SQ];   // sample_token
    for (int k = t; k < NTOTAL; k += T) {
        int idx = top_idx[k];
        out[1 + k]  = (float)g_tokens_flat[idx];
        out[60 + k] = g_scores_flat[idx];
    }
    __syncthreads();
    if (t == 0) {
        for (int k = 0; k < NTOTAL; ++k) {
            int p = g_parents_flat[top_idx[k] / TK];
            int mi;
            if (p == 0) {
                mi = 0;
            } else {
                int target = p - 1;
                int lo = 0, hi = NTOTAL;
                while (lo < hi) {
                    int mid = (lo + hi) >> 1;
                    if (top_idx[mid] < target) lo = mid + 1; else hi = mid;
                }
                mi = lo + 1;
            }
            mask_idx[k] = mi;
        }
        for (int r = 0; r < NTOTAL + 1; ++r)
            rows[r] = (1ULL << r) | 1ULL;
        for (int i = 0; i < NTOTAL; ++i) {
            int src = mask_idx[i];
            if (src > NTOTAL) src = NTOTAL;
            rows[i + 1] |= rows[src];
        }
    }
    __syncthreads();
    for (int e = t; e < (NTOTAL + 1) * (NTOTAL + 1); e += T) {
        int r = e / (NTOTAL + 1), c = e % (NTOTAL + 1);
        out[119 + e] = ((rows[r] >> c) & 1ULL) ? 1.0f : 0.0f;
    }
    for (int r = t; r < NTOTAL + 1; r += T)
        out[3719 + r] = (float)(__popcll(rows[r]) - 1);
}

// ---------------- launch ----------------
extern "C" void kernel_launch(void* const* d_in, const int* in_sizes, int n_in,
                              void* d_out, int out_size) {
    const float* hidden    = (const float*)d_in[0];
    const int*   input_ids = (const int*)d_in[1];
    const float* W_embed   = (const float*)d_in[2];
    const float* W_head    = (const float*)d_in[3];
    const float* W_fc      = (const float*)d_in[4];
    const float* b_fc      = (const float*)d_in[5];
    const float* W_m       = (const float*)d_in[6];
    const float* b_m       = (const float*)d_in[7];
    float* out = (float*)d_out;

    const int SM1  = 1  * KCHUNK * 4;   // 8 KB
    const int SM10 = TK * KCHUNK * 4;   // 80 KB

    // idempotent attribute setup (host API, graph-safe: not a graph node)
    cudaFuncSetAttribute(gemv2_kernel<TK, false, true >, cudaFuncAttributeMaxDynamicSharedMemorySize, SM10);
    cudaFuncSetAttribute(gemv2_kernel<TK, true,  false>, cudaFuncAttributeMaxDynamicSharedMemorySize, SM10);
    cudaFuncSetAttribute(gemv2_kernel<TK, false, false>, cudaFuncAttributeMaxDynamicSharedMemorySize, SM10);

    float *p_fc, *p_hid, *p_logits;
    int *p_cur, *p_out;
    cudaGetSymbolAddress((void**)&p_fc,     g_fc);
    cudaGetSymbolAddress((void**)&p_hid,    g_hid);
    cudaGetSymbolAddress((void**)&p_logits, g_logits);
    cudaGetSymbolAddress((void**)&p_cur,    g_cur_ids);
    cudaGetSymbolAddress((void**)&p_out,    g_out_ids);

    // ---- initial step (only last position matters) ----
    // X0 = concat(W_embed[input_ids[S]], hidden[:, S-1]); GATHER with
    // curids = &input_ids[S], outids = g_out_ids (zeroed by init_kernel),
    // Xbase = hidden row S-1 so outids[0]=0 selects exactly that row.
    init_kernel<<<1, 32>>>();
    gemv2_kernel<1, false, true ><<<HD / 32, 256, SM1>>>(
        hidden + (size_t)(SQ - 1) * HD, W_fc, b_fc, p_fc, HD, KK2,
        W_embed, input_ids + SQ, p_out);
    gemv2_kernel<1, true,  false><<<HD / 32, 256, SM1>>>(
        p_fc, W_m, b_m, p_hid, HD, HD, nullptr, nullptr, nullptr);
    gemv2_kernel<1, false, false><<<VOCAB / 32, 256, SM1>>>(
        p_hid, W_head, nullptr, p_logits, VOCAB, HD, nullptr, nullptr, nullptr);
    topk_p1_kernel<<<dim3(NCH, 1), 256>>>();
    topk_p2_kernel<<<1, 256>>>();
    post0_kernel<<<1, 32>>>();

    // ---- depth loop ----
    for (int i = 0; i < NDEPTH; ++i) {
        gemv2_kernel<TK, false, true ><<<HD / 32, 256, SM10>>>(
            p_hid, W_fc, b_fc, p_fc, HD, KK2, W_embed, p_cur, p_out);
        gemv2_kernel<TK, true,  false><<<HD / 32, 256, SM10>>>(
            p_fc, W_m, b_m, p_hid, HD, HD, nullptr, nullptr, nullptr);
        gemv2_kernel<TK, false, false><<<VOCAB / 32, 256, SM10>>>(
            p_hid, W_head, nullptr, p_logits, VOCAB, HD, nullptr, nullptr, nullptr);
        topk_p1_kernel<<<dim3(NCH, TK), 256>>>();
        topk_p2_kernel<<<TK, 256>>>();
        combine_kernel<<<1, 128>>>(i);
    }

    finalize_kernel<<<1, 256>>>(input_ids, out);
    (void)in_sizes; (void)n_in; (void)out_size;
}

// round 7
// speedup vs baseline: 1.9036x; 1.2324x over previous
#include <cuda_runtime.h>
#include <math.h>

#define SQ 1024
#define HD 4096
#define VOCAB 32000
#define KK2 8192          // 2*HD
#define TK 10
#define NDEPTH 5
#define NTOTAL 59
#define NFLAT (TK + NDEPTH*TK*TK)   // 510
#define NPAR (1 + NDEPTH*TK)        // 51
#define NCH 25            // chunks per row for top-k phase 1
#define CHUNK 1280        // VOCAB / NCH = 256*5
#define KCHUNK 2048       // GEMV K tile (floats)

// ---------------- scratch (device globals; no allocation allowed) ----------------
__device__ float g_fc[TK * HD];          // fc output
__device__ float g_hid[TK * HD];         // out_hidden (tanh)
__device__ float g_logits[TK * VOCAB];
__device__ float g_topk_p[TK * TK];      // per-row top-k log-probs
__device__ int   g_topk_i[TK * TK];      // per-row top-k vocab ids
__device__ float g_scores[TK];           // cumulative path scores
__device__ int   g_cs_index[TK];         // last topk_cs_index
__device__ int   g_cur_ids[TK];
__device__ int   g_out_ids[TK];
__device__ float g_scores_flat[NFLAT];
__device__ int   g_tokens_flat[NFLAT];
__device__ int   g_parents_flat[NPAR];
// top-k phase-1 partials
__device__ float g_pmax[TK * NCH];
__device__ float g_psum[TK * NCH];
__device__ float g_ptopv[TK * NCH * TK];
__device__ int   g_ptopi[TK * NCH * TK];

// ---------------- init: zero g_out_ids before the first GATHER GEMV ----------------
__global__ void init_kernel() {
    if (threadIdx.x < TK) g_out_ids[threadIdx.x] = 0;
}

// ---------------- GEMV with smem-staged X, 4 cols/warp, q-unroll 2 ----------------
// out[r][n] = act(sum_k X[r][k] * W[n][k] + b[n])
// GATHER mode builds X[r] = concat(W_embed[curids[r]], Xbase[outids[r]]) on the fly.
// __launch_bounds__(256, 2) caps regs at 128 so 2 blocks/SM co-reside (smem 80KB x2).
template <int R, bool TANH, bool GATHER>
__global__ void __launch_bounds__(256, 2)
gemv2_kernel(const float* __restrict__ Xbase,   // direct: X (R rows, stride K); gather: hidden base (stride HD)
             const float* __restrict__ W,
             const float* __restrict__ bias,
             float* __restrict__ out,
             int N, int K,
             const float* __restrict__ Wemb,
             const int* __restrict__ curids,
             const int* __restrict__ outids)
{
    extern __shared__ float sx[];            // R * KCHUNK floats
    float4* sx4 = (float4*)sx;
    const int t = threadIdx.x;
    const int warp = t >> 5, lane = t & 31;
    const int n0 = blockIdx.x * 32 + warp * 4;

    float acc[4][R];
#pragma unroll
    for (int c = 0; c < 4; ++c)
#pragma unroll
        for (int r = 0; r < R; ++r) acc[c][r] = 0.f;

    const int QC = KCHUNK / 4;               // 512 float4 per row-chunk
    const int nchunks = K / KCHUNK;
    for (int kc = 0; kc < nchunks; ++kc) {
        const int base_k = kc * KCHUNK;
        // ---- stage X chunk ----
        for (int idx = t; idx < R * QC; idx += 256) {
            int r = idx / QC;
            int kk4 = idx - r * QC;
            int k = base_k + kk4 * 4;
            float4 v;
            if (GATHER) {
                if (k < HD) {
                    int id = __ldg(curids + r);
                    v = *(const float4*)(Wemb + (size_t)id * HD + k);
                } else {
                    int orow = __ldg(outids + r);
                    v = *(const float4*)(Xbase + (size_t)orow * HD + (k - HD));
                }
            } else {
                v = *(const float4*)(Xbase + (size_t)r * K + k);
            }
            sx4[idx] = v;
        }
        __syncthreads();
        // ---- accumulate: 8 LDG.128 batched in flight, then FFMA burst ----
        const float4* w0 = (const float4*)(W + (size_t)(n0 + 0) * K + base_k);
        const float4* w1 = (const float4*)(W + (size_t)(n0 + 1) * K + base_k);
        const float4* w2 = (const float4*)(W + (size_t)(n0 + 2) * K + base_k);
        const float4* w3 = (const float4*)(W + (size_t)(n0 + 3) * K + base_k);
        for (int q = lane; q < QC; q += 64) {
            float4 A[2][4];
#pragma unroll
            for (int u = 0; u < 2; ++u) {
                int qq = q + u * 32;
                A[u][0] = __ldg(w0 + qq);
                A[u][1] = __ldg(w1 + qq);
                A[u][2] = __ldg(w2 + qq);
                A[u][3] = __ldg(w3 + qq);
            }
#pragma unroll
            for (int u = 0; u < 2; ++u) {
                int qq = q + u * 32;
#pragma unroll
                for (int r = 0; r < R; ++r) {
                    float4 xv = sx4[r * QC + qq];
                    acc[0][r] += A[u][0].x*xv.x; acc[0][r] += A[u][0].y*xv.y;
                    acc[0][r] += A[u][0].z*xv.z; acc[0][r] += A[u][0].w*xv.w;
                    acc[1][r] += A[u][1].x*xv.x; acc[1][r] += A[u][1].y*xv.y;
                    acc[1][r] += A[u][1].z*xv.z; acc[1][r] += A[u][1].w*xv.w;
                    acc[2][r] += A[u][2].x*xv.x; acc[2][r] += A[u][2].y*xv.y;
                    acc[2][r] += A[u][2].z*xv.z; acc[2][r] += A[u][2].w*xv.w;
                    acc[3][r] += A[u][3].x*xv.x; acc[3][r] += A[u][3].y*xv.y;
                    acc[3][r] += A[u][3].z*xv.z; acc[3][r] += A[u][3].w*xv.w;
                }
            }
        }
        __syncthreads();
    }
    // ---- warp reduce + write ----
#pragma unroll
    for (int c = 0; c < 4; ++c)
#pragma unroll
        for (int r = 0; r < R; ++r) {
            float a = acc[c][r];
#pragma unroll
            for (int off = 16; off > 0; off >>= 1)
                a += __shfl_down_sync(0xffffffffu, a, off);
            acc[c][r] = a;
        }
    if (lane == 0) {
#pragma unroll
        for (int c = 0; c < 4; ++c) {
            float b = bias ? bias[n0 + c] : 0.f;
#pragma unroll
            for (int r = 0; r < R; ++r) {
                float v = acc[c][r] + b;
                if (TANH) v = tanhf(v);
                out[(size_t)r * N + n0 + c] = v;
            }
        }
    }
}

// ---------------- top-k phase 1 ----------------
// grid (NCH, rows), 256 threads; chunk of 1280, 5 values/thread.
__global__ void __launch_bounds__(256) topk_p1_kernel() {
    const int chunk = blockIdx.x, r = blockIdx.y;
    const float* lp = g_logits + (size_t)r * VOCAB + chunk * CHUNK;
    const int gbase = chunk * CHUNK;
    __shared__ float sval[CHUNK];
    __shared__ float wred_v[8];
    __shared__ int   wred_i[8];
    const int t = threadIdx.x, lane = t & 31, wid = t >> 5;

    float v[5];
#pragma unroll
    for (int j = 0; j < 5; ++j) {
        float x = lp[t + j * 256];
        v[j] = x;
        sval[t + j * 256] = x;
    }
    // chunk max
    float m = fmaxf(fmaxf(fmaxf(v[0], v[1]), fmaxf(v[2], v[3])), v[4]);
#pragma unroll
    for (int off = 16; off > 0; off >>= 1)
        m = fmaxf(m, __shfl_xor_sync(0xffffffffu, m, off));
    if (lane == 0) wred_v[wid] = m;
    __syncthreads();
    if (t == 0) {
        float mm = wred_v[0];
#pragma unroll
        for (int w = 1; w < 8; ++w) mm = fmaxf(mm, wred_v[w]);
        wred_v[0] = mm;
    }
    __syncthreads();
    float cmax = wred_v[0];
    __syncthreads();
    // sum exp
    float s = 0.f;
#pragma unroll
    for (int j = 0; j < 5; ++j) s += expf(v[j] - cmax);
#pragma unroll
    for (int off = 16; off > 0; off >>= 1)
        s += __shfl_xor_sync(0xffffffffu, s, off);
    if (lane == 0) wred_v[wid] = s;
    __syncthreads();
    if (t == 0) {
        float ss = 0.f;
#pragma unroll
        for (int w = 0; w < 8; ++w) ss += wred_v[w];
        g_pmax[r * NCH + chunk] = cmax;
        g_psum[r * NCH + chunk] = ss;
    }
    __syncthreads();

    // 10 destructive argmax rounds (tie-break: lowest index)
    for (int k = 0; k < TK; ++k) {
        float bv = -INFINITY; int bi = 0x7fffffff;
#pragma unroll
        for (int j = 0; j < 5; ++j) {
            int l = t + j * 256;
            float x = sval[l];
            if (x > bv || (x == bv && l < bi)) { bv = x; bi = l; }
        }
#pragma unroll
        for (int off = 16; off > 0; off >>= 1) {
            float ov = __shfl_xor_sync(0xffffffffu, bv, off);
            int   oi = __shfl_xor_sync(0xffffffffu, bi, off);
            if (ov > bv || (ov == bv && oi < bi)) { bv = ov; bi = oi; }
        }
        if (lane == 0) { wred_v[wid] = bv; wred_i[wid] = bi; }
        __syncthreads();
        if (t == 0) {
            float Bv = wred_v[0]; int Bi = wred_i[0];
#pragma unroll
            for (int w = 1; w < 8; ++w) {
                float ov = wred_v[w]; int oi = wred_i[w];
                if (ov > Bv || (ov == Bv && oi < Bi)) { Bv = ov; Bi = oi; }
            }
            g_ptopv[(r * NCH + chunk) * TK + k] = Bv;
            g_ptopi[(r * NCH + chunk) * TK + k] = gbase + Bi;
            sval[Bi] = -INFINITY;
        }
        __syncthreads();
    }
}

// ---------------- top-k phase 2: merge 25*10 candidates + lse ----------------
__global__ void __launch_bounds__(256) topk_p2_kernel() {
    const int r = blockIdx.x, t = threadIdx.x, lane = t & 31, wid = t >> 5;
    const int NC = NCH * TK;   // 250
    __shared__ float cv[256];
    __shared__ int   ci[256];
    __shared__ float wv[8];
    __shared__ int   wi[8];
    __shared__ float s_lse;
    __shared__ int   s_win;

    cv[t] = (t < NC) ? g_ptopv[r * NC + t] : -INFINITY;
    ci[t] = (t < NC) ? g_ptopi[r * NC + t] : 0x7fffffff;
    if (t == 0) {
        float gmax = -INFINITY;
        for (int b = 0; b < NCH; ++b) gmax = fmaxf(gmax, g_pmax[r * NCH + b]);
        float sum = 0.f;
        for (int b = 0; b < NCH; ++b)
            sum += g_psum[r * NCH + b] * expf(g_pmax[r * NCH + b] - gmax);
        s_lse = gmax + logf(sum);
    }
    __syncthreads();
    float lse = s_lse;

    for (int k = 0; k < TK; ++k) {
        float bv = cv[t]; int bi = ci[t];
#pragma unroll
        for (int off = 16; off > 0; off >>= 1) {
            float ov = __shfl_xor_sync(0xffffffffu, bv, off);
            int   oi = __shfl_xor_sync(0xffffffffu, bi, off);
            if (ov > bv || (ov == bv && oi < bi)) { bv = ov; bi = oi; }
        }
        if (lane == 0) { wv[wid] = bv; wi[wid] = bi; }
        __syncthreads();
        if (t == 0) {
            float Bv = wv[0]; int Bi = wi[0];
#pragma unroll
            for (int w = 1; w < 8; ++w) {
                float ov = wv[w]; int oi = wi[w];
                if (ov > Bv || (ov == Bv && oi < Bi)) { Bv = ov; Bi = oi; }
            }
            g_topk_p[r * TK + k] = Bv - lse;
            g_topk_i[r * TK + k] = Bi;
            s_win = Bi;
        }
        __syncthreads();
        if (ci[t] == s_win) cv[t] = -INFINITY;
        __syncthreads();
    }
}

// ---------------- after the initial (pre-loop) top-k ----------------
__global__ void post0_kernel() {
    int t = threadIdx.x;
    if (t < TK) {
        float p = g_topk_p[t];
        int id = g_topk_i[t];
        g_scores[t] = p;
        g_scores_flat[t] = p;
        g_tokens_flat[t] = id;
        g_cur_ids[t] = id;
        g_cs_index[t] = t;
        g_out_ids[t] = 0;      // broadcast last_hidden (g_hid row 0)
        if (t == 0) g_parents_flat[0] = 0;
    }
}

// ---------------- cross-row merge for depth iteration `iter` ----------------
__global__ void combine_kernel(int iter) {
    __shared__ float cu[TK * TK];
    __shared__ float sc_old[TK];
    __shared__ int prev_cs[TK];
    int t = threadIdx.x;
    if (t < TK) { sc_old[t] = g_scores[t]; prev_cs[t] = g_cs_index[t]; }
    __syncthreads();
    if (t < TK * TK) cu[t] = g_topk_p[t] + sc_old[t / TK];
    __syncthreads();
    if (t < TK * TK) {
        g_scores_flat[TK + iter * 100 + t] = cu[t];
        g_tokens_flat[TK + iter * 100 + t] = g_topk_i[t];
    }
    if (t < TK) {
        int bias1 = (iter > 0) ? TK : 0;
        int bias2 = (iter > 1) ? (iter - 1) : 0;
        int bias = 1 + TK * TK * bias2 + bias1;
        g_parents_flat[1 + iter * TK + t] = prev_cs[t] + bias;
    }
    __syncthreads();
    if (t == 0) {
        bool used[TK * TK];
        for (int j = 0; j < TK * TK; ++j) used[j] = false;
        for (int k = 0; k < TK; ++k) {
            float best = -INFINITY; int bi = 0;
            for (int j = 0; j < TK * TK; ++j)
                if (!used[j] && cu[j] > best) { best = cu[j]; bi = j; }
            used[bi] = true;
            g_scores[k]   = best;
            g_cs_index[k] = bi;
            g_out_ids[k]  = bi / TK;
            g_cur_ids[k]  = g_topk_i[bi];
        }
    }
}

// ---------------- final: top-59, sort, parents, tree mask, outputs ----------------
__global__ void finalize_kernel(const int* __restrict__ input_ids, float* __restrict__ out) {
    __shared__ float sc[NFLAT];
    __shared__ int top_idx[NTOTAL];
    __shared__ int mask_idx[NTOTAL];
    __shared__ unsigned long long rows[NTOTAL + 1];
    int t = threadIdx.x, T = blockDim.x;
    for (int j = t; j < NFLAT; j += T) sc[j] = g_scores_flat[j];
    __syncthreads();
    if (t == 0) {
        for (int k = 0; k < NTOTAL; ++k) {
            float best = -INFINITY; int bi = 0;
            for (int j = 0; j < NFLAT; ++j)
                if (sc[j] > best) { best = sc[j]; bi = j; }
            top_idx[k] = bi;
            sc[bi] = -INFINITY;
        }
        for (int a = 1; a < NTOTAL; ++a) {
            int v = top_idx[a], b = a - 1;
            while (b >= 0 && top_idx[b] > v) { top_idx[b + 1] = top_idx[b]; --b; }
            top_idx[b + 1] = v;
        }
    }
    __syncthreads();
    if (t == 0) out[0] = (float)input_ids[SQ];   // sample_token
    for (int k = t; k < NTOTAL; k += T) {
        int idx = top_idx[k];
        out[1 + k]  = (float)g_tokens_flat[idx];
        out[60 + k] = g_scores_flat[idx];
    }
    __syncthreads();
    if (t == 0) {
        for (int k = 0; k < NTOTAL; ++k) {
            int p = g_parents_flat[top_idx[k] / TK];
            int mi;
            if (p == 0) {
                mi = 0;
            } else {
                int target = p - 1;
                int lo = 0, hi = NTOTAL;
                while (lo < hi) {
                    int mid = (lo + hi) >> 1;
                    if (top_idx[mid] < target) lo = mid + 1; else hi = mid;
                }
                mi = lo + 1;
            }
            mask_idx[k] = mi;
        }
        for (int r = 0; r < NTOTAL + 1; ++r)
            rows[r] = (1ULL << r) | 1ULL;
        for (int i = 0; i < NTOTAL; ++i) {
            int src = mask_idx[i];
            if (src > NTOTAL) src = NTOTAL;
            rows[i + 1] |= rows[src];
        }
    }
    __syncthreads();
    for (int e = t; e < (NTOTAL + 1) * (NTOTAL + 1); e += T) {
        int r = e / (NTOTAL + 1), c = e % (NTOTAL + 1);
        out[119 + e] = ((rows[r] >> c) & 1ULL) ? 1.0f : 0.0f;
    }
    for (int r = t; r < NTOTAL + 1; r += T)
        out[3719 + r] = (float)(__popcll(rows[r]) - 1);
}

// ---------------- launch ----------------
extern "C" void kernel_launch(void* const* d_in, const int* in_sizes, int n_in,
                              void* d_out, int out_size) {
    const float* hidden    = (const float*)d_in[0];
    const int*   input_ids = (const int*)d_in[1];
    const float* W_embed   = (const float*)d_in[2];
    const float* W_head    = (const float*)d_in[3];
    const float* W_fc      = (const float*)d_in[4];
    const float* b_fc      = (const float*)d_in[5];
    const float* W_m       = (const float*)d_in[6];
    const float* b_m       = (const float*)d_in[7];
    float* out = (float*)d_out;

    const int SM1  = 1  * KCHUNK * 4;   // 8 KB
    const int SM10 = TK * KCHUNK * 4;   // 80 KB

    // idempotent attribute setup (host API, graph-safe: not a graph node)
    cudaFuncSetAttribute(gemv2_kernel<TK, false, true >, cudaFuncAttributeMaxDynamicSharedMemorySize, SM10);
    cudaFuncSetAttribute(gemv2_kernel<TK, true,  false>, cudaFuncAttributeMaxDynamicSharedMemorySize, SM10);
    cudaFuncSetAttribute(gemv2_kernel<TK, false, false>, cudaFuncAttributeMaxDynamicSharedMemorySize, SM10);

    float *p_fc, *p_hid, *p_logits;
    int *p_cur, *p_out;
    cudaGetSymbolAddress((void**)&p_fc,     g_fc);
    cudaGetSymbolAddress((void**)&p_hid,    g_hid);
    cudaGetSymbolAddress((void**)&p_logits, g_logits);
    cudaGetSymbolAddress((void**)&p_cur,    g_cur_ids);
    cudaGetSymbolAddress((void**)&p_out,    g_out_ids);

    // ---- initial step (only last position matters) ----
    init_kernel<<<1, 32>>>();
    gemv2_kernel<1, false, true ><<<HD / 32, 256, SM1>>>(
        hidden + (size_t)(SQ - 1) * HD, W_fc, b_fc, p_fc, HD, KK2,
        W_embed, input_ids + SQ, p_out);
    gemv2_kernel<1, true,  false><<<HD / 32, 256, SM1>>>(
        p_fc, W_m, b_m, p_hid, HD, HD, nullptr, nullptr, nullptr);
    gemv2_kernel<1, false, false><<<VOCAB / 32, 256, SM1>>>(
        p_hid, W_head, nullptr, p_logits, VOCAB, HD, nullptr, nullptr, nullptr);
    topk_p1_kernel<<<dim3(NCH, 1), 256>>>();
    topk_p2_kernel<<<1, 256>>>();
    post0_kernel<<<1, 32>>>();

    // ---- depth loop ----
    for (int i = 0; i < NDEPTH; ++i) {
        gemv2_kernel<TK, false, true ><<<HD / 32, 256, SM10>>>(
            p_hid, W_fc, b_fc, p_fc, HD, KK2, W_embed, p_cur, p_out);
        gemv2_kernel<TK, true,  false><<<HD / 32, 256, SM10>>>(
            p_fc, W_m, b_m, p_hid, HD, HD, nullptr, nullptr, nullptr);
        gemv2_kernel<TK, false, false><<<VOCAB / 32, 256, SM10>>>(
            p_hid, W_head, nullptr, p_logits, VOCAB, HD, nullptr, nullptr, nullptr);
        topk_p1_kernel<<<dim3(NCH, TK), 256>>>();
        topk_p2_kernel<<<TK, 256>>>();
        combine_kernel<<<1, 128>>>(i);
    }

    finalize_kernel<<<1, 256>>>(input_ids, out);
    (void)in_sizes; (void)n_in; (void)out_size;
}